// round 13
// baseline (speedup 1.0000x reference)
#include <cuda_runtime.h>
#include <cuda_bf16.h>

// Problem constants
#define B_ 8
#define T_ 2048
#define I_ 64
#define H_ 128
#define G3H 384                 // 3*H
#define TRI 2098176             // T*(T+1)/2
#define COUT_ELEMS (B_*T_*H_)   // 2097152

// Scratch (allocation-free rule: __device__ globals)
__device__ float g_xw[B_*T_*G3H];   // input projections (B,T,3H)
__device__ float g_h [B_*T_*H_];    // GRU hidden states
__device__ float g_e [B_*T_];       // attention logits
__device__ float g_w [B_*T_];       // exp(e - max)
__device__ float g_D [B_*T_];       // cumsum of w
__device__ float g_S [B_*16*H_];    // per-chunk partial sums for c_out scan

// ---------------------------------------------------------------------------
// f32x2 packed-FMA helpers
// ---------------------------------------------------------------------------
__device__ __forceinline__ void fma2(unsigned long long& acc,
                                     unsigned long long a,
                                     unsigned long long b) {
    asm("fma.rn.f32x2 %0, %1, %2, %0;" : "+l"(acc) : "l"(a), "l"(b));
}
__device__ __forceinline__ float pairsum(unsigned long long v) {
    float lo, hi;
    asm("mov.b64 {%0,%1}, %2;" : "=f"(lo), "=f"(hi) : "l"(v));
    return lo + hi;
}

// Fast activations: MUFU EX2 + MUFU RCP (~2 ULP, proven 5e-7 end-to-end)
#define LOG2E 1.4426950408889634f
__device__ __forceinline__ float fast_sigmoid(float x) {
    float e, r;
    asm("ex2.approx.f32 %0, %1;" : "=f"(e) : "f"(-LOG2E * x));
    asm("rcp.approx.f32 %0, %1;" : "=f"(r) : "f"(e + 1.0f));
    return r;
}
__device__ __forceinline__ float fast_tanh(float x) {
    float e, r;
    asm("ex2.approx.f32 %0, %1;" : "=f"(e) : "f"((2.0f * LOG2E) * x));
    asm("rcp.approx.f32 %0, %1;" : "=f"(r) : "f"(e + 1.0f));
    return fmaf(-2.0f, r, 1.0f);
}

// ---------------------------------------------------------------------------
// 0) Dummy kernel: pads launch slots so ncu's window (launch idx 3) hits gru.
// ---------------------------------------------------------------------------
__global__ void dummy_kernel() {}

// ---------------------------------------------------------------------------
// 1) Input projection: xw[bt, j] = sum_k x[bt,k] * W_ih[j,k] + b_ih[j]
// ---------------------------------------------------------------------------
__global__ __launch_bounds__(384, 1)
void proj_kernel(const float* __restrict__ x,
                 const float* __restrict__ W_ih,
                 const float* __restrict__ b_ih) {
    const int row = threadIdx.x;          // 0..383
    const int bt0 = blockIdx.x * 64;
    __shared__ __align__(16) float xs[64 * I_];

    unsigned long long w[32];             // 64 floats of W_ih row
    const unsigned long long* wr =
        reinterpret_cast<const unsigned long long*>(W_ih + row * I_);
#pragma unroll
    for (int k = 0; k < 32; k++) w[k] = wr[k];
    const float bi = b_ih[row];

    const float4* xg = reinterpret_cast<const float4*>(x + (size_t)bt0 * I_);
    for (int i = threadIdx.x; i < 64 * I_ / 4; i += 384)
        reinterpret_cast<float4*>(xs)[i] = xg[i];
    __syncthreads();

    for (int j = 0; j < 64; j++) {
        unsigned long long a0 = 0ull, a1 = 0ull;
        const ulonglong2* hp = reinterpret_cast<const ulonglong2*>(xs + j * I_);
#pragma unroll
        for (int k = 0; k < 16; k++) {
            ulonglong2 hv = hp[k];
            fma2(a0, w[2 * k], hv.x);
            fma2(a1, w[2 * k + 1], hv.y);
        }
        g_xw[(size_t)(bt0 + j) * G3H + row] = pairsum(a0) + pairsum(a1) + bi;
    }
}

// ---------------------------------------------------------------------------
// 2) GRU recurrence, pair-split + phase-split. 256 threads; thread 2u+half
//    owns k-half [half*64, half*64+64) of all 3 gate rows (192 weight floats
//    in regs). Phase 1: r,z dots -> shfl -> sigmoids. Phase 2: n dot (h
//    re-read from smem) overlaps phase-1's shfl/MUFU latency. One barrier,
//    double-buffered h_sh.
// ---------------------------------------------------------------------------
__global__ __launch_bounds__(256, 1)
void gru_kernel(const float* __restrict__ W_hh,
                const float* __restrict__ b_hh) {
    const int b = blockIdx.x;
    const int tid = threadIdx.x;
    const int u = tid >> 1;               // unit 0..127
    const int half = tid & 1;             // k-half
    const int k0 = half * 64;

    __shared__ __align__(16) float h_sh[2][H_];   // double buffer

    // weight halves: rows u (r), u+128 (z), u+256 (n), cols [k0, k0+64)
    unsigned long long wr[32], wz[32], wn[32];
    {
        const unsigned long long* pr =
            reinterpret_cast<const unsigned long long*>(W_hh + (size_t)u * H_ + k0);
        const unsigned long long* pz =
            reinterpret_cast<const unsigned long long*>(W_hh + (size_t)(u + H_) * H_ + k0);
        const unsigned long long* pn =
            reinterpret_cast<const unsigned long long*>(W_hh + (size_t)(u + 2 * H_) * H_ + k0);
#pragma unroll
        for (int k = 0; k < 32; k++) { wr[k] = pr[k]; wz[k] = pz[k]; wn[k] = pn[k]; }
    }
    const float br = b_hh[u];
    const float bz = b_hh[u + H_];
    const float bn = b_hh[u + 2 * H_];

    if (tid < H_) h_sh[0][tid] = 0.0f;
    float h_reg = 0.0f;                   // both pair threads carry h[u]

    const float* xwb = g_xw + (size_t)b * T_ * G3H;
    float xr_n = __ldg(xwb + u);
    float xz_n = __ldg(xwb + u + H_);
    float xn_n = __ldg(xwb + u + 2 * H_);
    __syncthreads();

    int par = 0;
    for (int t = 0; t < T_; t++) {
        const float xr = xr_n, xz = xz_n, xn = xn_n;
        const float* xwt = xwb + (size_t)((t + 1 < T_) ? t + 1 : t) * G3H;
        xr_n = __ldg(xwt + u);
        xz_n = __ldg(xwt + u + H_);
        xn_n = __ldg(xwt + u + 2 * H_);

        const ulonglong2* hp =
            reinterpret_cast<const ulonglong2*>(&h_sh[par][k0]);

        // ---- phase 1: r and z dots ----
        unsigned long long ar = 0ull, az = 0ull;
#pragma unroll
        for (int k = 0; k < 16; k++) {
            ulonglong2 hv = hp[k];
            fma2(ar, wr[2 * k], hv.x); fma2(ar, wr[2 * k + 1], hv.y);
            fma2(az, wz[2 * k], hv.x); fma2(az, wz[2 * k + 1], hv.y);
        }
        float dr = pairsum(ar);
        float dz = pairsum(az);
        dr += __shfl_xor_sync(0xffffffffu, dr, 1);
        dz += __shfl_xor_sync(0xffffffffu, dz, 1);
        const float r = fast_sigmoid(xr + dr + br);
        const float z = fast_sigmoid(xz + dz + bz);

        // ---- phase 2: n dot (independent of phase-1 shfl/MUFU; overlaps) ----
        unsigned long long an = 0ull;
#pragma unroll
        for (int k = 0; k < 16; k++) {
            ulonglong2 hv = hp[k];        // re-read: keeps reg pressure low
            fma2(an, wn[2 * k], hv.x);
            fma2(an, wn[2 * k + 1], hv.y);
        }
        float dn = pairsum(an);
        dn += __shfl_xor_sync(0xffffffffu, dn, 1);

        const float n = fast_tanh(fmaf(r, dn + bn, xn));
        const float hn = fmaf(z, h_reg - n, n);      // (1-z)n + z h
        h_reg = hn;
        if (!half) {
            h_sh[par ^ 1][u] = hn;
            g_h[((size_t)b * T_ + t) * H_ + u] = hn;
        }
        __syncthreads();   // one barrier: write(par^1) vs next-iter read(par^1)
        par ^= 1;
    }
}

// ---------------------------------------------------------------------------
// 3) e[bt] = dot(h[bt,:], W_lin) + b_lin   (one warp per bt)
// ---------------------------------------------------------------------------
__global__ __launch_bounds__(128)
void e_kernel(const float* __restrict__ W_lin,
              const float* __restrict__ b_lin) {
    const int bt = blockIdx.x * 4 + (threadIdx.x >> 5);
    const int lane = threadIdx.x & 31;
    float4 hv = reinterpret_cast<const float4*>(g_h + (size_t)bt * H_)[lane];
    float4 wv = reinterpret_cast<const float4*>(W_lin)[lane];
    float s = hv.x * wv.x + hv.y * wv.y + hv.z * wv.z + hv.w * wv.w;
#pragma unroll
    for (int o = 16; o; o >>= 1) s += __shfl_xor_sync(0xffffffffu, s, o);
    if (lane == 0) g_e[bt] = s + b_lin[0];
}

// ---------------------------------------------------------------------------
// 4) Per batch: M = max(e), w = exp(e-M), D = inclusive cumsum(w)
// ---------------------------------------------------------------------------
__global__ __launch_bounds__(512, 1)
void scan_kernel() {
    const int b = blockIdx.x;
    const int tid = threadIdx.x;
    __shared__ float sh[512];

    const float* eb = g_e + b * T_;
    float4 ev = reinterpret_cast<const float4*>(eb)[tid];

    float m = fmaxf(fmaxf(ev.x, ev.y), fmaxf(ev.z, ev.w));
    sh[tid] = m;
    __syncthreads();
#pragma unroll
    for (int o = 256; o; o >>= 1) {
        if (tid < o) sh[tid] = fmaxf(sh[tid], sh[tid + o]);
        __syncthreads();
    }
    const float M = sh[0];
    __syncthreads();

    const float w0 = __expf(ev.x - M);
    const float w1 = __expf(ev.y - M);
    const float w2 = __expf(ev.z - M);
    const float w3 = __expf(ev.w - M);
    const float p0 = w0, p1 = p0 + w1, p2 = p1 + w2, p3 = p2 + w3;

    sh[tid] = p3;
    __syncthreads();
    for (int o = 1; o < 512; o <<= 1) {     // Hillis-Steele inclusive scan
        float v = (tid >= o) ? sh[tid - o] : 0.0f;
        __syncthreads();
        sh[tid] += v;
        __syncthreads();
    }
    const float base = sh[tid] - p3;        // exclusive prefix of this thread

    reinterpret_cast<float4*>(g_w + b * T_)[tid] = make_float4(w0, w1, w2, w3);
    reinterpret_cast<float4*>(g_D + b * T_)[tid] =
        make_float4(base + p0, base + p1, base + p2, base + p3);
}

// ---------------------------------------------------------------------------
// 5) c_out prefix scan, 2-pass chunked (16 chunks of 128 steps per batch)
// ---------------------------------------------------------------------------
__global__ __launch_bounds__(128)
void cout_partial_kernel() {
    const int c = blockIdx.x, b = blockIdx.y, tid = threadIdx.x;
    const float* wb = g_w + b * T_;
    float acc = 0.0f;
    for (int t = c * 128; t < c * 128 + 128; t++)
        acc = fmaf(__ldg(wb + t), __ldg(&g_h[((size_t)b * T_ + t) * H_ + tid]), acc);
    g_S[(b * 16 + c) * H_ + tid] = acc;
}

__global__ __launch_bounds__(128)
void cout_main_kernel(float* __restrict__ out) {
    const int c = blockIdx.x, b = blockIdx.y, tid = threadIdx.x;
    float acc = 0.0f;
    for (int c2 = 0; c2 < c; c2++) acc += g_S[(b * 16 + c2) * H_ + tid];
    const float* wb = g_w + b * T_;
    const float* Db = g_D + b * T_;
    for (int t = c * 128; t < c * 128 + 128; t++) {
        acc = fmaf(__ldg(wb + t), __ldg(&g_h[((size_t)b * T_ + t) * H_ + tid]), acc);
        out[((size_t)b * T_ + t) * H_ + tid] = acc * (1.0f / __ldg(Db + t));
    }
}

// ---------------------------------------------------------------------------
// 6) alpha_out[b, t(t+1)/2 + s] = w[b,s] / D[b,t],  s = 0..t
// ---------------------------------------------------------------------------
__global__ __launch_bounds__(256)
void alpha_kernel(float* __restrict__ out) {
    const int t = blockIdx.x, b = blockIdx.y;
    const float invD = 1.0f / g_D[b * T_ + t];
    const float* wb = g_w + b * T_;
    float* dst = out + COUT_ELEMS + (size_t)b * TRI + ((size_t)t * (t + 1)) / 2;
    for (int s = threadIdx.x; s <= t; s += 256)
        dst[s] = wb[s] * invD;
}

// ---------------------------------------------------------------------------
extern "C" void kernel_launch(void* const* d_in, const int* in_sizes, int n_in,
                              void* d_out, int out_size) {
    const float* x     = (const float*)d_in[0];
    const float* W_ih  = (const float*)d_in[1];
    const float* W_hh  = (const float*)d_in[2];
    const float* b_ih  = (const float*)d_in[3];
    const float* b_hh  = (const float*)d_in[4];
    const float* W_lin = (const float*)d_in[5];
    const float* b_lin = (const float*)d_in[6];
    float* out = (float*)d_out;

    // Launch idx: 0=proj, 1-2=dummy, 3=gru (profiler captures idx 3), 4+=rest
    proj_kernel<<<256, 384>>>(x, W_ih, b_ih);
    dummy_kernel<<<1, 32>>>();
    dummy_kernel<<<1, 32>>>();
    gru_kernel<<<B_, 256>>>(W_hh, b_hh);
    e_kernel<<<(B_ * T_) / 4, 128>>>(W_lin, b_lin);
    scan_kernel<<<B_, 512>>>();
    cout_partial_kernel<<<dim3(16, B_), 128>>>();
    cout_main_kernel<<<dim3(16, B_), 128>>>(out);
    alpha_kernel<<<dim3(T_, B_), 256>>>(out);
}

// round 15
// speedup vs baseline: 1.3513x; 1.3513x over previous
#include <cuda_runtime.h>
#include <cuda_bf16.h>

// Problem constants
#define B_ 8
#define T_ 2048
#define I_ 64
#define H_ 128
#define G3H 384                 // 3*H
#define TRI 2098176             // T*(T+1)/2
#define COUT_ELEMS (B_*T_*H_)   // 2097152

// Scratch (allocation-free rule: __device__ globals)
__device__ float g_xw[B_*T_*G3H];   // input projections (B,T,3H)
__device__ float g_h [B_*T_*H_];    // GRU hidden states
__device__ float g_e [B_*T_];       // attention logits
__device__ float g_w [B_*T_];       // exp(e - max)
__device__ float g_D [B_*T_];       // cumsum of w
__device__ float g_S [B_*16*H_];    // per-chunk partial sums for c_out scan

// ---------------------------------------------------------------------------
// f32x2 packed-FMA helpers
// ---------------------------------------------------------------------------
__device__ __forceinline__ void fma2(unsigned long long& acc,
                                     unsigned long long a,
                                     unsigned long long b) {
    asm("fma.rn.f32x2 %0, %1, %2, %0;" : "+l"(acc) : "l"(a), "l"(b));
}
__device__ __forceinline__ float pairsum(unsigned long long v) {
    float lo, hi;
    asm("mov.b64 {%0,%1}, %2;" : "=f"(lo), "=f"(hi) : "l"(v));
    return lo + hi;
}
__device__ __forceinline__ unsigned long long pack2(float lo, float hi) {
    unsigned long long v;
    asm("mov.b64 %0, {%1, %2};" : "=l"(v) : "f"(lo), "f"(hi));
    return v;
}

// Fast activations: MUFU EX2 + MUFU RCP (~2 ULP, proven 5e-7 end-to-end)
#define LOG2E 1.4426950408889634f
__device__ __forceinline__ float fast_sigmoid(float x) {
    float e, r;
    asm("ex2.approx.f32 %0, %1;" : "=f"(e) : "f"(-LOG2E * x));
    asm("rcp.approx.f32 %0, %1;" : "=f"(r) : "f"(e + 1.0f));
    return r;
}
__device__ __forceinline__ float fast_tanh(float x) {
    float e, r;
    asm("ex2.approx.f32 %0, %1;" : "=f"(e) : "f"((2.0f * LOG2E) * x));
    asm("rcp.approx.f32 %0, %1;" : "=f"(r) : "f"(e + 1.0f));
    return fmaf(-2.0f, r, 1.0f);
}

// ---------------------------------------------------------------------------
// 0) Dummy kernel: pads launch slots so ncu's window (launch idx 3) hits gru.
// ---------------------------------------------------------------------------
__global__ void dummy_kernel() {}

// ---------------------------------------------------------------------------
// 1) Input projection: xw[bt, j] = sum_k x[bt,k] * W_ih[j,k] + b_ih[j]
// ---------------------------------------------------------------------------
__global__ __launch_bounds__(384, 1)
void proj_kernel(const float* __restrict__ x,
                 const float* __restrict__ W_ih,
                 const float* __restrict__ b_ih) {
    const int row = threadIdx.x;          // 0..383
    const int bt0 = blockIdx.x * 64;
    __shared__ __align__(16) float xs[64 * I_];

    unsigned long long w[32];             // 64 floats of W_ih row
    const unsigned long long* wr =
        reinterpret_cast<const unsigned long long*>(W_ih + row * I_);
#pragma unroll
    for (int k = 0; k < 32; k++) w[k] = wr[k];
    const float bi = b_ih[row];

    const float4* xg = reinterpret_cast<const float4*>(x + (size_t)bt0 * I_);
    for (int i = threadIdx.x; i < 64 * I_ / 4; i += 384)
        reinterpret_cast<float4*>(xs)[i] = xg[i];
    __syncthreads();

    for (int j = 0; j < 64; j++) {
        unsigned long long a0 = 0ull, a1 = 0ull;
        const ulonglong2* hp = reinterpret_cast<const ulonglong2*>(xs + j * I_);
#pragma unroll
        for (int k = 0; k < 16; k++) {
            ulonglong2 hv = hp[k];
            fma2(a0, w[2 * k], hv.x);
            fma2(a1, w[2 * k + 1], hv.y);
        }
        g_xw[(size_t)(bt0 + j) * G3H + row] = pairsum(a0) + pairsum(a1) + bi;
    }
}

// ---------------------------------------------------------------------------
// 2) GRU recurrence, pair-split (R11 proven structure). 256 threads; thread
//    2u+half owns k-half [half*64, half*64+64) of all 3 gate rows (192 weight
//    floats in regs). Single interleaved dot loop, accumulators bias-seeded
//    (br/2 etc. so the pair shfl reconstructs the full bias for free), one
//    barrier, double-buffered h_sh.
// ---------------------------------------------------------------------------
__global__ __launch_bounds__(256, 1)
void gru_kernel(const float* __restrict__ W_hh,
                const float* __restrict__ b_hh) {
    const int b = blockIdx.x;
    const int tid = threadIdx.x;
    const int u = tid >> 1;               // unit 0..127
    const int half = tid & 1;             // k-half
    const int k0 = half * 64;

    __shared__ __align__(16) float h_sh[2][H_];   // double buffer

    // weight halves: rows u (r), u+128 (z), u+256 (n), cols [k0, k0+64)
    unsigned long long wr[32], wz[32], wn[32];
    {
        const unsigned long long* pr =
            reinterpret_cast<const unsigned long long*>(W_hh + (size_t)u * H_ + k0);
        const unsigned long long* pz =
            reinterpret_cast<const unsigned long long*>(W_hh + (size_t)(u + H_) * H_ + k0);
        const unsigned long long* pn =
            reinterpret_cast<const unsigned long long*>(W_hh + (size_t)(u + 2 * H_) * H_ + k0);
#pragma unroll
        for (int k = 0; k < 32; k++) { wr[k] = pr[k]; wz[k] = pz[k]; wn[k] = pn[k]; }
    }
    // half-bias seeds: after shfl_xor the two halves sum to the full bias
    const unsigned long long sr = pack2(0.5f * b_hh[u], 0.0f);
    const unsigned long long sz = pack2(0.5f * b_hh[u + H_], 0.0f);
    const unsigned long long sn = pack2(0.5f * b_hh[u + 2 * H_], 0.0f);

    if (tid < H_) h_sh[0][tid] = 0.0f;
    float h_reg = 0.0f;                   // both pair threads carry h[u]

    const float* xwb = g_xw + (size_t)b * T_ * G3H;
    float xr_n = __ldg(xwb + u);
    float xz_n = __ldg(xwb + u + H_);
    float xn_n = __ldg(xwb + u + 2 * H_);
    __syncthreads();

    int par = 0;
    for (int t = 0; t < T_; t++) {
        const float xr = xr_n, xz = xz_n, xn = xn_n;
        const float* xwt = xwb + (size_t)((t + 1 < T_) ? t + 1 : t) * G3H;
        xr_n = __ldg(xwt + u);
        xz_n = __ldg(xwt + u + H_);
        xn_n = __ldg(xwt + u + 2 * H_);

        unsigned long long ar = sr, az = sz, an = sn;
        const ulonglong2* hp =
            reinterpret_cast<const ulonglong2*>(&h_sh[par][k0]);
#pragma unroll
        for (int k = 0; k < 16; k++) {
            ulonglong2 hv = hp[k];
            fma2(ar, wr[2 * k], hv.x); fma2(ar, wr[2 * k + 1], hv.y);
            fma2(az, wz[2 * k], hv.x); fma2(az, wz[2 * k + 1], hv.y);
            fma2(an, wn[2 * k], hv.x); fma2(an, wn[2 * k + 1], hv.y);
        }
        float dr = pairsum(ar);
        float dz = pairsum(az);
        float dn = pairsum(an);
        dr += __shfl_xor_sync(0xffffffffu, dr, 1);   // combine halves (+bias)
        dz += __shfl_xor_sync(0xffffffffu, dz, 1);
        dn += __shfl_xor_sync(0xffffffffu, dn, 1);

        const float r = fast_sigmoid(xr + dr);
        const float z = fast_sigmoid(xz + dz);
        const float n = fast_tanh(fmaf(r, dn, xn));
        const float hn = fmaf(z, h_reg - n, n);      // (1-z)n + z h
        h_reg = hn;
        if (!half) {
            h_sh[par ^ 1][u] = hn;
            g_h[((size_t)b * T_ + t) * H_ + u] = hn;
        }
        __syncthreads();   // one barrier: write(par^1) vs next-iter read(par^1)
        par ^= 1;
    }
}

// ---------------------------------------------------------------------------
// 3) e[bt] = dot(h[bt,:], W_lin) + b_lin   (one warp per bt)
// ---------------------------------------------------------------------------
__global__ __launch_bounds__(128)
void e_kernel(const float* __restrict__ W_lin,
              const float* __restrict__ b_lin) {
    const int bt = blockIdx.x * 4 + (threadIdx.x >> 5);
    const int lane = threadIdx.x & 31;
    float4 hv = reinterpret_cast<const float4*>(g_h + (size_t)bt * H_)[lane];
    float4 wv = reinterpret_cast<const float4*>(W_lin)[lane];
    float s = hv.x * wv.x + hv.y * wv.y + hv.z * wv.z + hv.w * wv.w;
#pragma unroll
    for (int o = 16; o; o >>= 1) s += __shfl_xor_sync(0xffffffffu, s, o);
    if (lane == 0) g_e[bt] = s + b_lin[0];
}

// ---------------------------------------------------------------------------
// 4) Per batch: M = max(e), w = exp(e-M), D = inclusive cumsum(w)
// ---------------------------------------------------------------------------
__global__ __launch_bounds__(512, 1)
void scan_kernel() {
    const int b = blockIdx.x;
    const int tid = threadIdx.x;
    __shared__ float sh[512];

    const float* eb = g_e + b * T_;
    float4 ev = reinterpret_cast<const float4*>(eb)[tid];

    float m = fmaxf(fmaxf(ev.x, ev.y), fmaxf(ev.z, ev.w));
    sh[tid] = m;
    __syncthreads();
#pragma unroll
    for (int o = 256; o; o >>= 1) {
        if (tid < o) sh[tid] = fmaxf(sh[tid], sh[tid + o]);
        __syncthreads();
    }
    const float M = sh[0];
    __syncthreads();

    const float w0 = __expf(ev.x - M);
    const float w1 = __expf(ev.y - M);
    const float w2 = __expf(ev.z - M);
    const float w3 = __expf(ev.w - M);
    const float p0 = w0, p1 = p0 + w1, p2 = p1 + w2, p3 = p2 + w3;

    sh[tid] = p3;
    __syncthreads();
    for (int o = 1; o < 512; o <<= 1) {     // Hillis-Steele inclusive scan
        float v = (tid >= o) ? sh[tid - o] : 0.0f;
        __syncthreads();
        sh[tid] += v;
        __syncthreads();
    }
    const float base = sh[tid] - p3;        // exclusive prefix of this thread

    reinterpret_cast<float4*>(g_w + b * T_)[tid] = make_float4(w0, w1, w2, w3);
    reinterpret_cast<float4*>(g_D + b * T_)[tid] =
        make_float4(base + p0, base + p1, base + p2, base + p3);
}

// ---------------------------------------------------------------------------
// 5) c_out prefix scan, 2-pass chunked (16 chunks of 128 steps per batch)
// ---------------------------------------------------------------------------
__global__ __launch_bounds__(128)
void cout_partial_kernel() {
    const int c = blockIdx.x, b = blockIdx.y, tid = threadIdx.x;
    const float* wb = g_w + b * T_;
    float acc = 0.0f;
    for (int t = c * 128; t < c * 128 + 128; t++)
        acc = fmaf(__ldg(wb + t), __ldg(&g_h[((size_t)b * T_ + t) * H_ + tid]), acc);
    g_S[(b * 16 + c) * H_ + tid] = acc;
}

__global__ __launch_bounds__(128)
void cout_main_kernel(float* __restrict__ out) {
    const int c = blockIdx.x, b = blockIdx.y, tid = threadIdx.x;
    float acc = 0.0f;
    for (int c2 = 0; c2 < c; c2++) acc += g_S[(b * 16 + c2) * H_ + tid];
    const float* wb = g_w + b * T_;
    const float* Db = g_D + b * T_;
    for (int t = c * 128; t < c * 128 + 128; t++) {
        acc = fmaf(__ldg(wb + t), __ldg(&g_h[((size_t)b * T_ + t) * H_ + tid]), acc);
        out[((size_t)b * T_ + t) * H_ + tid] = acc * (1.0f / __ldg(Db + t));
    }
}

// ---------------------------------------------------------------------------
// 6) alpha_out[b, t(t+1)/2 + s] = w[b,s] / D[b,t],  s = 0..t
// ---------------------------------------------------------------------------
__global__ __launch_bounds__(256)
void alpha_kernel(float* __restrict__ out) {
    const int t = blockIdx.x, b = blockIdx.y;
    const float invD = 1.0f / g_D[b * T_ + t];
    const float* wb = g_w + b * T_;
    float* dst = out + COUT_ELEMS + (size_t)b * TRI + ((size_t)t * (t + 1)) / 2;
    for (int s = threadIdx.x; s <= t; s += 256)
        dst[s] = wb[s] * invD;
}

// ---------------------------------------------------------------------------
extern "C" void kernel_launch(void* const* d_in, const int* in_sizes, int n_in,
                              void* d_out, int out_size) {
    const float* x     = (const float*)d_in[0];
    const float* W_ih  = (const float*)d_in[1];
    const float* W_hh  = (const float*)d_in[2];
    const float* b_ih  = (const float*)d_in[3];
    const float* b_hh  = (const float*)d_in[4];
    const float* W_lin = (const float*)d_in[5];
    const float* b_lin = (const float*)d_in[6];
    float* out = (float*)d_out;

    // Launch idx: 0=proj, 1-2=dummy, 3=gru (profiler captures idx 3), 4+=rest
    proj_kernel<<<256, 384>>>(x, W_ih, b_ih);
    dummy_kernel<<<1, 32>>>();
    dummy_kernel<<<1, 32>>>();
    gru_kernel<<<B_, 256>>>(W_hh, b_hh);
    e_kernel<<<(B_ * T_) / 4, 128>>>(W_lin, b_lin);
    scan_kernel<<<B_, 512>>>();
    cout_partial_kernel<<<dim3(16, B_), 128>>>();
    cout_main_kernel<<<dim3(16, B_), 128>>>(out);
    alpha_kernel<<<dim3(T_, B_), 256>>>(out);
}